// round 5
// baseline (speedup 1.0000x reference)
#include <cuda_runtime.h>

#define N_NODES 50000
#define N_EDGES 600000
#define REL_NUM 500
#define E_HID   128

// output layout: x_e [50000*128] | rel_out [500*128] | res_att [600000]
#define REL_OFF (N_NODES * E_HID)
#define RES_OFF (REL_OFF + REL_NUM * E_HID)

// scratch (device globals: no allocations allowed)
__device__ float    g_remb[REL_NUM * E_HID];  // r_emb = rel_emb @ ww_w.T
__device__ float    g_dp[N_EDGES];            // per-edge dot products
__device__ unsigned g_max_bits;               // order-encoded float max
__device__ float    g_sum;                    // softmax denominator
// CSR-by-dst build
__device__ int      g_cnt[N_NODES];           // in-degree histogram
__device__ int      g_row[N_NODES + 1];       // row offsets
__device__ int      g_cur[N_NODES];           // fill cursors
__device__ int      g_perm[N_EDGES];          // edge ids sorted by dst

__device__ __forceinline__ unsigned enc_f(float f) {
    unsigned u = __float_as_uint(f);
    return (u & 0x80000000u) ? ~u : (u | 0x80000000u);
}
__device__ __forceinline__ float dec_f(unsigned u) {
    return (u & 0x80000000u) ? __uint_as_float(u & 0x7FFFFFFFu)
                             : __uint_as_float(~u);
}

// ---------------------------------------------------------------------------
// K0: copy res_att, zero histogram, reset scalars (x_e is fully written later)
// ---------------------------------------------------------------------------
__global__ void k_init(float* __restrict__ out, const float* __restrict__ res_att) {
    int i = blockIdx.x * blockDim.x + threadIdx.x;
    int stride = gridDim.x * blockDim.x;
    for (int j = i; j < N_EDGES; j += stride) out[RES_OFF + j] = res_att[j];
    for (int j = i; j < N_NODES; j += stride) g_cnt[j] = 0;
    if (i == 0) { g_max_bits = 0u; g_sum = 0.f; }
}

// ---------------------------------------------------------------------------
// K1: r_emb = rel_emb @ ww_w.T (scratch);  rel_out = rel_emb @ rel_w.T (out)
// ---------------------------------------------------------------------------
__global__ void k_rel(const float* __restrict__ rel_emb,
                      const float* __restrict__ ww_w,
                      const float* __restrict__ rel_w,
                      float* __restrict__ out) {
    __shared__ float row[E_HID];
    int r = blockIdx.x, t = threadIdx.x;
    row[t] = rel_emb[r * E_HID + t];
    __syncthreads();
    float a = 0.f, b = 0.f;
#pragma unroll 8
    for (int k = 0; k < E_HID; k++) {
        float v = row[k];
        a = fmaf(v, ww_w[t * E_HID + k], a);
        b = fmaf(v, rel_w[t * E_HID + k], b);
    }
    g_remb[r * E_HID + t] = a;
    out[REL_OFF + r * E_HID + t] = b;
}

// ---------------------------------------------------------------------------
// K2: in-degree histogram over dst
// ---------------------------------------------------------------------------
__global__ void k_hist(const int* __restrict__ ei) {
    int i = blockIdx.x * blockDim.x + threadIdx.x;
    int stride = gridDim.x * blockDim.x;
    for (int e = i; e < N_EDGES; e += stride)
        atomicAdd(&g_cnt[ei[N_EDGES + e]], 1);
}

// ---------------------------------------------------------------------------
// K3: single-block exclusive scan of g_cnt -> g_row, g_cur
// ---------------------------------------------------------------------------
__global__ void k_scan() {
    __shared__ int warp_sums[32];
    __shared__ int s_carry;
    int t = threadIdx.x;              // 1024 threads
    int lane = t & 31, w = t >> 5;
    if (t == 0) s_carry = 0;
    __syncthreads();
    for (int base = 0; base < N_NODES; base += 1024) {
        int idx = base + t;
        int v = (idx < N_NODES) ? g_cnt[idx] : 0;
        int xv = v;
#pragma unroll
        for (int o = 1; o < 32; o <<= 1) {
            int y = __shfl_up_sync(0xffffffffu, xv, o);
            if (lane >= o) xv += y;
        }
        if (lane == 31) warp_sums[w] = xv;
        __syncthreads();
        if (w == 0) {
            int ws = warp_sums[lane];
#pragma unroll
            for (int o = 1; o < 32; o <<= 1) {
                int y = __shfl_up_sync(0xffffffffu, ws, o);
                if (lane >= o) ws += y;
            }
            warp_sums[lane] = ws;
        }
        __syncthreads();
        int excl = xv - v + (w > 0 ? warp_sums[w - 1] : 0) + s_carry;
        if (idx < N_NODES) { g_row[idx] = excl; g_cur[idx] = excl; }
        __syncthreads();
        if (t == 1023) s_carry = excl + v;
        __syncthreads();
    }
    if (t == 0) g_row[N_NODES] = N_EDGES;
}

// ---------------------------------------------------------------------------
// K4: fill permutation (edge ids grouped by dst)
// ---------------------------------------------------------------------------
__global__ void k_fill(const int* __restrict__ ei) {
    int i = blockIdx.x * blockDim.x + threadIdx.x;
    int stride = gridDim.x * blockDim.x;
    for (int e = i; e < N_EDGES; e += stride) {
        int pos = atomicAdd(&g_cur[ei[N_EDGES + e]], 1);
        g_perm[pos] = e;
    }
}

// ---------------------------------------------------------------------------
// K5: per-edge dot product. One warp per edge, float4 per lane.
// ---------------------------------------------------------------------------
__global__ void k_dp(const float* __restrict__ x,
                     const int* __restrict__ ei,
                     const int* __restrict__ et) {
    int e = (int)(((long long)blockIdx.x * blockDim.x + threadIdx.x) >> 5);
    int lane = threadIdx.x & 31;
    if (e >= N_EDGES) return;
    int src = ei[e];
    int dst = ei[N_EDGES + e];
    int r = et[e];
    const float4 xs = *(const float4*)(x + (long long)src * E_HID + lane * 4);
    const float4 rr = *(const float4*)(g_remb + (long long)r * E_HID + lane * 4);
    const float4 xt = *(const float4*)(x + (long long)dst * E_HID + lane * 4);
    float p = (xs.x + rr.x) * xt.x + (xs.y + rr.y) * xt.y
            + (xs.z + rr.z) * xt.z + (xs.w + rr.w) * xt.w;
#pragma unroll
    for (int o = 16; o; o >>= 1) p += __shfl_xor_sync(0xffffffffu, p, o);
    if (lane == 0) g_dp[e] = p;
}

// ---------------------------------------------------------------------------
// K6: global max of g_dp
// ---------------------------------------------------------------------------
__global__ void k_max() {
    float m = -3.4e38f;
    int i = blockIdx.x * blockDim.x + threadIdx.x;
    int stride = gridDim.x * blockDim.x;
    for (int j = i; j < N_EDGES; j += stride) m = fmaxf(m, g_dp[j]);
#pragma unroll
    for (int o = 16; o; o >>= 1) m = fmaxf(m, __shfl_xor_sync(0xffffffffu, m, o));
    __shared__ float sm[32];
    if ((threadIdx.x & 31) == 0) sm[threadIdx.x >> 5] = m;
    __syncthreads();
    if (threadIdx.x < 32) {
        m = (threadIdx.x < (blockDim.x >> 5)) ? sm[threadIdx.x] : -3.4e38f;
#pragma unroll
        for (int o = 16; o; o >>= 1) m = fmaxf(m, __shfl_xor_sync(0xffffffffu, m, o));
        if (threadIdx.x == 0) atomicMax(&g_max_bits, enc_f(m));
    }
}

// ---------------------------------------------------------------------------
// K7: softmax denominator sum(exp(dp - max))
// ---------------------------------------------------------------------------
__global__ void k_sum() {
    float m = dec_f(g_max_bits);
    float s = 0.f;
    int i = blockIdx.x * blockDim.x + threadIdx.x;
    int stride = gridDim.x * blockDim.x;
    for (int j = i; j < N_EDGES; j += stride) s += __expf(g_dp[j] - m);
#pragma unroll
    for (int o = 16; o; o >>= 1) s += __shfl_xor_sync(0xffffffffu, s, o);
    __shared__ float sm[32];
    if ((threadIdx.x & 31) == 0) sm[threadIdx.x >> 5] = s;
    __syncthreads();
    if (threadIdx.x < 32) {
        s = (threadIdx.x < (blockDim.x >> 5)) ? sm[threadIdx.x] : 0.f;
#pragma unroll
        for (int o = 16; o; o >>= 1) s += __shfl_xor_sync(0xffffffffu, s, o);
        if (threadIdx.x == 0) atomicAdd(&g_sum, s);
    }
}

// ---------------------------------------------------------------------------
// K8: CSR aggregation. One warp per node: accumulate coef*(x[src]+r_emb)
// over its in-edges in registers, single store + fused ReLU. No atomics.
// ---------------------------------------------------------------------------
__global__ void k_agg(const float* __restrict__ x,
                      const int* __restrict__ ei,
                      const int* __restrict__ et,
                      float* __restrict__ out) {
    int n = (int)(((long long)blockIdx.x * blockDim.x + threadIdx.x) >> 5);
    int lane = threadIdx.x & 31;
    if (n >= N_NODES) return;
    float m = dec_f(g_max_bits);
    float inv = 1.0f / g_sum;
    int beg = g_row[n], end = g_row[n + 1];
    float ax = 0.f, ay = 0.f, az = 0.f, aw = 0.f;
    for (int i = beg; i < end; i++) {
        int e = g_perm[i];                       // lane-uniform broadcast loads
        float coef = __expf(g_dp[e] - m) * inv;
        int src = ei[e];
        int r = et[e];
        const float4 xs = *(const float4*)(x + (long long)src * E_HID + lane * 4);
        const float4 rr = *(const float4*)(g_remb + (long long)r * E_HID + lane * 4);
        ax = fmaf(coef, xs.x + rr.x, ax);
        ay = fmaf(coef, xs.y + rr.y, ay);
        az = fmaf(coef, xs.z + rr.z, az);
        aw = fmaf(coef, xs.w + rr.w, aw);
    }
    float4* o = (float4*)(out + (long long)n * E_HID) + lane;
    *o = make_float4(fmaxf(ax, 0.f), fmaxf(ay, 0.f), fmaxf(az, 0.f), fmaxf(aw, 0.f));
}

extern "C" void kernel_launch(void* const* d_in, const int* in_sizes, int n_in,
                              void* d_out, int out_size) {
    const float* x       = (const float*)d_in[0];   // [50000,128] f32
    const int*   ei      = (const int*)d_in[1];     // [2,600000] int32
    const int*   et      = (const int*)d_in[2];     // [600000] int32
    const float* rel_emb = (const float*)d_in[3];   // [500,128]
    const float* res_att = (const float*)d_in[4];   // [600000]
    const float* ww_w    = (const float*)d_in[5];   // [128,128]
    const float* rel_w   = (const float*)d_in[6];   // [128,128]
    float* out = (float*)d_out;

    (void)in_sizes; (void)n_in; (void)out_size;

    k_init<<<2048, 256>>>(out, res_att);
    k_rel<<<REL_NUM, E_HID>>>(rel_emb, ww_w, rel_w, out);

    // CSR-by-dst build
    k_hist<<<1024, 256>>>(ei);
    k_scan<<<1, 1024>>>();
    k_fill<<<1024, 256>>>(ei);

    // attention logits + global softmax stats
    const int edge_blocks = (N_EDGES * 32 + 255) / 256;  // warp per edge
    k_dp<<<edge_blocks, 256>>>(x, ei, et);
    k_max<<<512, 256>>>();
    k_sum<<<512, 256>>>();

    // atomic-free aggregation (ReLU fused)
    const int node_blocks = (N_NODES * 32 + 255) / 256;  // warp per node
    k_agg<<<node_blocks, 256>>>(x, ei, et, out);
}

// round 6
// speedup vs baseline: 1.1506x; 1.1506x over previous
#include <cuda_runtime.h>

#define N_NODES 50000
#define N_EDGES 600000
#define REL_NUM 500
#define E_HID   128

#define SCAN_B   1024
#define SCAN_NB  ((N_NODES + SCAN_B - 1) / SCAN_B)   // 49

// output layout: x_e [50000*128] | rel_out [500*128] | res_att [600000]
#define REL_OFF (N_NODES * E_HID)
#define RES_OFF (REL_OFF + REL_NUM * E_HID)

// scratch (device globals: no allocations allowed)
__device__ float    g_remb[REL_NUM * E_HID];  // r_emb = rel_emb @ ww_w.T
__device__ float    g_dp[N_EDGES];            // per-edge dot products
__device__ unsigned g_max_bits;               // order-encoded float max
__device__ float    g_sum;                    // softmax denominator
// CSR-by-dst build
__device__ int      g_cnt[N_NODES];           // in-degree histogram
__device__ int      g_row[N_NODES + 1];       // row offsets
__device__ int      g_cur[N_NODES];           // fill cursors
__device__ int      g_perm[N_EDGES];          // edge ids sorted by dst
__device__ int      g_bsum[SCAN_NB];          // per-block scan totals
__device__ int      g_boff[SCAN_NB];          // exclusive block offsets

__device__ __forceinline__ unsigned enc_f(float f) {
    unsigned u = __float_as_uint(f);
    return (u & 0x80000000u) ? ~u : (u | 0x80000000u);
}
__device__ __forceinline__ float dec_f(unsigned u) {
    return (u & 0x80000000u) ? __uint_as_float(u & 0x7FFFFFFFu)
                             : __uint_as_float(~u);
}

// ---------------------------------------------------------------------------
// K0: copy res_att, zero histogram, reset scalars
// ---------------------------------------------------------------------------
__global__ void k_init(float* __restrict__ out, const float* __restrict__ res_att) {
    int i = blockIdx.x * blockDim.x + threadIdx.x;
    int stride = gridDim.x * blockDim.x;
    for (int j = i; j < N_EDGES; j += stride) out[RES_OFF + j] = res_att[j];
    for (int j = i; j < N_NODES; j += stride) g_cnt[j] = 0;
    if (i == 0) { g_max_bits = 0u; g_sum = 0.f; }
}

// ---------------------------------------------------------------------------
// K1: r_emb = rel_emb @ ww_w.T (scratch);  rel_out = rel_emb @ rel_w.T (out)
// ---------------------------------------------------------------------------
__global__ void k_rel(const float* __restrict__ rel_emb,
                      const float* __restrict__ ww_w,
                      const float* __restrict__ rel_w,
                      float* __restrict__ out) {
    __shared__ float row[E_HID];
    int r = blockIdx.x, t = threadIdx.x;
    row[t] = rel_emb[r * E_HID + t];
    __syncthreads();
    float a = 0.f, b = 0.f;
#pragma unroll 8
    for (int k = 0; k < E_HID; k++) {
        float v = row[k];
        a = fmaf(v, ww_w[t * E_HID + k], a);
        b = fmaf(v, rel_w[t * E_HID + k], b);
    }
    g_remb[r * E_HID + t] = a;
    out[REL_OFF + r * E_HID + t] = b;
}

// ---------------------------------------------------------------------------
// K2: in-degree histogram over dst
// ---------------------------------------------------------------------------
__global__ void k_hist(const int* __restrict__ ei) {
    int i = blockIdx.x * blockDim.x + threadIdx.x;
    int stride = gridDim.x * blockDim.x;
    for (int e = i; e < N_EDGES; e += stride)
        atomicAdd(&g_cnt[ei[N_EDGES + e]], 1);
}

// ---------------------------------------------------------------------------
// K3a: per-block exclusive scan (49 blocks x 1024); write block totals
// ---------------------------------------------------------------------------
__global__ void k_scan_a() {
    __shared__ int warp_sums[32];
    int t = threadIdx.x;
    int lane = t & 31, w = t >> 5;
    int idx = blockIdx.x * SCAN_B + t;
    int v = (idx < N_NODES) ? g_cnt[idx] : 0;
    int xv = v;
#pragma unroll
    for (int o = 1; o < 32; o <<= 1) {
        int y = __shfl_up_sync(0xffffffffu, xv, o);
        if (lane >= o) xv += y;
    }
    if (lane == 31) warp_sums[w] = xv;
    __syncthreads();
    if (w == 0) {
        int ws = warp_sums[lane];
#pragma unroll
        for (int o = 1; o < 32; o <<= 1) {
            int y = __shfl_up_sync(0xffffffffu, ws, o);
            if (lane >= o) ws += y;
        }
        warp_sums[lane] = ws;
    }
    __syncthreads();
    int excl = xv - v + (w > 0 ? warp_sums[w - 1] : 0);
    if (idx < N_NODES) g_row[idx] = excl;
    if (t == SCAN_B - 1) g_bsum[blockIdx.x] = excl + v;
}

// ---------------------------------------------------------------------------
// K3b: one small block scans the 49 block totals (exclusive)
// ---------------------------------------------------------------------------
__global__ void k_scan_b() {
    __shared__ int warp_sums[2];
    int t = threadIdx.x;             // 64 threads
    int lane = t & 31, w = t >> 5;
    int v = (t < SCAN_NB) ? g_bsum[t] : 0;
    int xv = v;
#pragma unroll
    for (int o = 1; o < 32; o <<= 1) {
        int y = __shfl_up_sync(0xffffffffu, xv, o);
        if (lane >= o) xv += y;
    }
    if (lane == 31) warp_sums[w] = xv;
    __syncthreads();
    int excl = xv - v + (w > 0 ? warp_sums[0] : 0);
    if (t < SCAN_NB) g_boff[t] = excl;
}

// ---------------------------------------------------------------------------
// K3c: apply block offsets; materialize g_row + g_cur + sentinel
// ---------------------------------------------------------------------------
__global__ void k_scan_c() {
    int idx = blockIdx.x * SCAN_B + threadIdx.x;
    if (idx < N_NODES) {
        int v = g_row[idx] + g_boff[blockIdx.x];
        g_row[idx] = v;
        g_cur[idx] = v;
    }
    if (idx == 0) g_row[N_NODES] = N_EDGES;
}

// ---------------------------------------------------------------------------
// K4: fill permutation (edge ids grouped by dst)
// ---------------------------------------------------------------------------
__global__ void k_fill(const int* __restrict__ ei) {
    int i = blockIdx.x * blockDim.x + threadIdx.x;
    int stride = gridDim.x * blockDim.x;
    for (int e = i; e < N_EDGES; e += stride) {
        int pos = atomicAdd(&g_cur[ei[N_EDGES + e]], 1);
        g_perm[pos] = e;
    }
}

// ---------------------------------------------------------------------------
// K5: per-edge dot product. One warp per edge, float4 per lane.
// ---------------------------------------------------------------------------
__global__ void k_dp(const float* __restrict__ x,
                     const int* __restrict__ ei,
                     const int* __restrict__ et) {
    int e = (int)(((long long)blockIdx.x * blockDim.x + threadIdx.x) >> 5);
    int lane = threadIdx.x & 31;
    if (e >= N_EDGES) return;
    int src = ei[e];
    int dst = ei[N_EDGES + e];
    int r = et[e];
    const float4 xs = *(const float4*)(x + (long long)src * E_HID + lane * 4);
    const float4 rr = *(const float4*)(g_remb + (long long)r * E_HID + lane * 4);
    const float4 xt = *(const float4*)(x + (long long)dst * E_HID + lane * 4);
    float p = (xs.x + rr.x) * xt.x + (xs.y + rr.y) * xt.y
            + (xs.z + rr.z) * xt.z + (xs.w + rr.w) * xt.w;
#pragma unroll
    for (int o = 16; o; o >>= 1) p += __shfl_xor_sync(0xffffffffu, p, o);
    if (lane == 0) g_dp[e] = p;
}

// ---------------------------------------------------------------------------
// K6: global max of g_dp
// ---------------------------------------------------------------------------
__global__ void k_max() {
    float m = -3.4e38f;
    int i = blockIdx.x * blockDim.x + threadIdx.x;
    int stride = gridDim.x * blockDim.x;
    for (int j = i; j < N_EDGES; j += stride) m = fmaxf(m, g_dp[j]);
#pragma unroll
    for (int o = 16; o; o >>= 1) m = fmaxf(m, __shfl_xor_sync(0xffffffffu, m, o));
    __shared__ float sm[32];
    if ((threadIdx.x & 31) == 0) sm[threadIdx.x >> 5] = m;
    __syncthreads();
    if (threadIdx.x < 32) {
        m = (threadIdx.x < (blockDim.x >> 5)) ? sm[threadIdx.x] : -3.4e38f;
#pragma unroll
        for (int o = 16; o; o >>= 1) m = fmaxf(m, __shfl_xor_sync(0xffffffffu, m, o));
        if (threadIdx.x == 0) atomicMax(&g_max_bits, enc_f(m));
    }
}

// ---------------------------------------------------------------------------
// K7: softmax denominator sum(exp(dp - max))
// ---------------------------------------------------------------------------
__global__ void k_sum() {
    float m = dec_f(g_max_bits);
    float s = 0.f;
    int i = blockIdx.x * blockDim.x + threadIdx.x;
    int stride = gridDim.x * blockDim.x;
    for (int j = i; j < N_EDGES; j += stride) s += __expf(g_dp[j] - m);
#pragma unroll
    for (int o = 16; o; o >>= 1) s += __shfl_xor_sync(0xffffffffu, s, o);
    __shared__ float sm[32];
    if ((threadIdx.x & 31) == 0) sm[threadIdx.x >> 5] = s;
    __syncthreads();
    if (threadIdx.x < 32) {
        s = (threadIdx.x < (blockDim.x >> 5)) ? sm[threadIdx.x] : 0.f;
#pragma unroll
        for (int o = 16; o; o >>= 1) s += __shfl_xor_sync(0xffffffffu, s, o);
        if (threadIdx.x == 0) atomicAdd(&g_sum, s);
    }
}

// ---------------------------------------------------------------------------
// K8: CSR aggregation. One warp per node: accumulate coef*(x[src]+r_emb)
// over its in-edges in registers, single store + fused ReLU. No atomics.
// ---------------------------------------------------------------------------
__global__ void k_agg(const float* __restrict__ x,
                      const int* __restrict__ ei,
                      const int* __restrict__ et,
                      float* __restrict__ out) {
    int n = (int)(((long long)blockIdx.x * blockDim.x + threadIdx.x) >> 5);
    int lane = threadIdx.x & 31;
    if (n >= N_NODES) return;
    float m = dec_f(g_max_bits);
    float inv = 1.0f / g_sum;
    int beg = g_row[n], end = g_row[n + 1];
    float ax = 0.f, ay = 0.f, az = 0.f, aw = 0.f;
    for (int i = beg; i < end; i++) {
        int e = g_perm[i];                       // lane-uniform broadcast loads
        float coef = __expf(g_dp[e] - m) * inv;
        int src = ei[e];
        int r = et[e];
        const float4 xs = *(const float4*)(x + (long long)src * E_HID + lane * 4);
        const float4 rr = *(const float4*)(g_remb + (long long)r * E_HID + lane * 4);
        ax = fmaf(coef, xs.x + rr.x, ax);
        ay = fmaf(coef, xs.y + rr.y, ay);
        az = fmaf(coef, xs.z + rr.z, az);
        aw = fmaf(coef, xs.w + rr.w, aw);
    }
    float4* o = (float4*)(out + (long long)n * E_HID) + lane;
    *o = make_float4(fmaxf(ax, 0.f), fmaxf(ay, 0.f), fmaxf(az, 0.f), fmaxf(aw, 0.f));
}

extern "C" void kernel_launch(void* const* d_in, const int* in_sizes, int n_in,
                              void* d_out, int out_size) {
    const float* x       = (const float*)d_in[0];   // [50000,128] f32
    const int*   ei      = (const int*)d_in[1];     // [2,600000] int32
    const int*   et      = (const int*)d_in[2];     // [600000] int32
    const float* rel_emb = (const float*)d_in[3];   // [500,128]
    const float* res_att = (const float*)d_in[4];   // [600000]
    const float* ww_w    = (const float*)d_in[5];   // [128,128]
    const float* rel_w   = (const float*)d_in[6];   // [128,128]
    float* out = (float*)d_out;

    (void)in_sizes; (void)n_in; (void)out_size;

    k_init<<<2048, 256>>>(out, res_att);
    k_rel<<<REL_NUM, E_HID>>>(rel_emb, ww_w, rel_w, out);

    // CSR-by-dst build (parallel 3-phase scan)
    k_hist<<<1024, 256>>>(ei);
    k_scan_a<<<SCAN_NB, SCAN_B>>>();
    k_scan_b<<<1, 64>>>();
    k_scan_c<<<SCAN_NB, SCAN_B>>>();
    k_fill<<<1024, 256>>>(ei);

    // attention logits + global softmax stats
    const int edge_blocks = (N_EDGES * 32 + 255) / 256;  // warp per edge
    k_dp<<<edge_blocks, 256>>>(x, ei, et);
    k_max<<<512, 256>>>();
    k_sum<<<512, 256>>>();

    // atomic-free aggregation (ReLU fused)
    const int node_blocks = (N_NODES * 32 + 255) / 256;  // warp per node
    k_agg<<<node_blocks, 256>>>(x, ei, et, out);
}

// round 7
// speedup vs baseline: 1.2342x; 1.0726x over previous
#include <cuda_runtime.h>

#define N_NODES 50000
#define N_EDGES 600000
#define REL_NUM 500
#define E_HID   128

#define SCAN_B   1024
#define SCAN_NB  ((N_NODES + SCAN_B - 1) / SCAN_B)   // 49

#define DP_BLK    256
#define DP_WARPS  (DP_BLK / 32)
#define DP_NB     ((N_NODES + DP_WARPS - 1) / DP_WARPS)  // 6250

// output layout: x_e [50000*128] | rel_out [500*128] | res_att [600000]
#define REL_OFF (N_NODES * E_HID)
#define RES_OFF (REL_OFF + REL_NUM * E_HID)

// scratch (device globals: no allocations allowed)
__device__ float g_remb[REL_NUM * E_HID];  // r_emb = rel_emb @ ww_w.T
__device__ float g_dp[N_EDGES];            // dot products, CSR order
__device__ int   g_pack[N_EDGES];          // (rel<<17)|src, CSR order
__device__ int   g_cnt[N_NODES];           // in-degree histogram
__device__ int   g_row[N_NODES + 1];       // CSR row offsets
__device__ int   g_cur[N_NODES];           // fill cursors
__device__ int   g_bsum[SCAN_NB];
__device__ int   g_boff[SCAN_NB];
__device__ float g_pmax[DP_NB];            // per-block softmax partials
__device__ float g_psum[DP_NB];
__device__ float g_m;                      // global max
__device__ float g_inv;                    // 1 / global sum

// ---------------------------------------------------------------------------
// K0: copy res_att, zero histogram
// ---------------------------------------------------------------------------
__global__ void k_init(float* __restrict__ out, const float* __restrict__ res_att) {
    int i = blockIdx.x * blockDim.x + threadIdx.x;
    int stride = gridDim.x * blockDim.x;
    for (int j = i; j < N_EDGES; j += stride) out[RES_OFF + j] = res_att[j];
    for (int j = i; j < N_NODES; j += stride) g_cnt[j] = 0;
}

// ---------------------------------------------------------------------------
// K1: r_emb = rel_emb @ ww_w.T (scratch);  rel_out = rel_emb @ rel_w.T (out)
// ---------------------------------------------------------------------------
__global__ void k_rel(const float* __restrict__ rel_emb,
                      const float* __restrict__ ww_w,
                      const float* __restrict__ rel_w,
                      float* __restrict__ out) {
    __shared__ float row[E_HID];
    int r = blockIdx.x, t = threadIdx.x;
    row[t] = rel_emb[r * E_HID + t];
    __syncthreads();
    float a = 0.f, b = 0.f;
#pragma unroll 8
    for (int k = 0; k < E_HID; k++) {
        float v = row[k];
        a = fmaf(v, ww_w[t * E_HID + k], a);
        b = fmaf(v, rel_w[t * E_HID + k], b);
    }
    g_remb[r * E_HID + t] = a;
    out[REL_OFF + r * E_HID + t] = b;
}

// ---------------------------------------------------------------------------
// K2: in-degree histogram over dst
// ---------------------------------------------------------------------------
__global__ void k_hist(const int* __restrict__ ei) {
    int i = blockIdx.x * blockDim.x + threadIdx.x;
    int stride = gridDim.x * blockDim.x;
    for (int e = i; e < N_EDGES; e += stride)
        atomicAdd(&g_cnt[ei[N_EDGES + e]], 1);
}

// ---------------------------------------------------------------------------
// K3a/b/c: 3-phase exclusive scan of g_cnt -> g_row, g_cur
// ---------------------------------------------------------------------------
__global__ void k_scan_a() {
    __shared__ int warp_sums[32];
    int t = threadIdx.x;
    int lane = t & 31, w = t >> 5;
    int idx = blockIdx.x * SCAN_B + t;
    int v = (idx < N_NODES) ? g_cnt[idx] : 0;
    int xv = v;
#pragma unroll
    for (int o = 1; o < 32; o <<= 1) {
        int y = __shfl_up_sync(0xffffffffu, xv, o);
        if (lane >= o) xv += y;
    }
    if (lane == 31) warp_sums[w] = xv;
    __syncthreads();
    if (w == 0) {
        int ws = warp_sums[lane];
#pragma unroll
        for (int o = 1; o < 32; o <<= 1) {
            int y = __shfl_up_sync(0xffffffffu, ws, o);
            if (lane >= o) ws += y;
        }
        warp_sums[lane] = ws;
    }
    __syncthreads();
    int excl = xv - v + (w > 0 ? warp_sums[w - 1] : 0);
    if (idx < N_NODES) g_row[idx] = excl;
    if (t == SCAN_B - 1) g_bsum[blockIdx.x] = excl + v;
}

__global__ void k_scan_b() {
    __shared__ int warp_sums[2];
    int t = threadIdx.x;             // 64 threads
    int lane = t & 31, w = t >> 5;
    int v = (t < SCAN_NB) ? g_bsum[t] : 0;
    int xv = v;
#pragma unroll
    for (int o = 1; o < 32; o <<= 1) {
        int y = __shfl_up_sync(0xffffffffu, xv, o);
        if (lane >= o) xv += y;
    }
    if (lane == 31) warp_sums[w] = xv;
    __syncthreads();
    int excl = xv - v + (w > 0 ? warp_sums[0] : 0);
    if (t < SCAN_NB) g_boff[t] = excl;
}

__global__ void k_scan_c() {
    int idx = blockIdx.x * SCAN_B + threadIdx.x;
    if (idx < N_NODES) {
        int v = g_row[idx] + g_boff[blockIdx.x];
        g_row[idx] = v;
        g_cur[idx] = v;
    }
    if (idx == 0) g_row[N_NODES] = N_EDGES;
}

// ---------------------------------------------------------------------------
// K4: fill packed CSR payload: (rel<<17)|src per slot, grouped by dst
// ---------------------------------------------------------------------------
__global__ void k_fill(const int* __restrict__ ei, const int* __restrict__ et) {
    int i = blockIdx.x * blockDim.x + threadIdx.x;
    int stride = gridDim.x * blockDim.x;
    for (int e = i; e < N_EDGES; e += stride) {
        int dst = ei[N_EDGES + e];
        int pos = atomicAdd(&g_cur[dst], 1);
        g_pack[pos] = ei[e] | (et[e] << 17);
    }
}

// ---------------------------------------------------------------------------
// K5: CSR dot products + fused online softmax partials.
// Warp per node: x[dst] loaded ONCE into registers; per in-edge gather
// x[src]+r_emb, warp-reduce dot, store dp in CSR order, maintain (m,s).
// ---------------------------------------------------------------------------
__global__ void k_dp_csr(const float* __restrict__ x) {
    __shared__ float sm_m[DP_WARPS], sm_s[DP_WARPS];
    int n = (int)(((long long)blockIdx.x * blockDim.x + threadIdx.x) >> 5);
    int lane = threadIdx.x & 31;
    int w = threadIdx.x >> 5;

    float m_w = -3.4e38f, s_w = 0.f;
    if (n < N_NODES) {
        int beg = g_row[n], end = g_row[n + 1];
        const float4 xd = *(const float4*)(x + (long long)n * E_HID + lane * 4);
        for (int i = beg; i < end; i++) {
            int pk = g_pack[i];
            int src = pk & 0x1FFFF;
            int r = pk >> 17;
            const float4 xs = *(const float4*)(x + (long long)src * E_HID + lane * 4);
            const float4 rr = *(const float4*)(g_remb + (long long)r * E_HID + lane * 4);
            float p = (xs.x + rr.x) * xd.x + (xs.y + rr.y) * xd.y
                    + (xs.z + rr.z) * xd.z + (xs.w + rr.w) * xd.w;
#pragma unroll
            for (int o = 16; o; o >>= 1) p += __shfl_xor_sync(0xffffffffu, p, o);
            if (lane == 0) g_dp[i] = p;
            // online (m, s) — p identical on all lanes after xor-reduce
            if (p > m_w) { s_w *= __expf(m_w - p); m_w = p; }
            s_w += __expf(p - m_w);
        }
    }
    if (lane == 0) { sm_m[w] = m_w; sm_s[w] = s_w; }
    __syncthreads();
    if (threadIdx.x == 0) {
        float M = sm_m[0], S = sm_s[0];
#pragma unroll
        for (int k = 1; k < DP_WARPS; k++) {
            float m2 = sm_m[k], s2 = sm_s[k];
            float M2 = fmaxf(M, m2);
            S = S * __expf(M - M2) + s2 * __expf(m2 - M2);
            M = M2;
        }
        g_pmax[blockIdx.x] = M;
        g_psum[blockIdx.x] = S;
    }
}

// ---------------------------------------------------------------------------
// K6: combine per-block (m, s) partials -> g_m, g_inv. Single block.
// ---------------------------------------------------------------------------
__global__ void k_combine() {
    __shared__ float sm_m[32], sm_s[32];
    int t = threadIdx.x;             // 1024
    int lane = t & 31, w = t >> 5;
    float M = -3.4e38f, S = 0.f;
    for (int i = t; i < DP_NB; i += 1024) {
        float m2 = g_pmax[i], s2 = g_psum[i];
        float M2 = fmaxf(M, m2);
        S = S * __expf(M - M2) + s2 * __expf(m2 - M2);
        M = M2;
    }
#pragma unroll
    for (int o = 16; o; o >>= 1) {
        float m2 = __shfl_xor_sync(0xffffffffu, M, o);
        float s2 = __shfl_xor_sync(0xffffffffu, S, o);
        float M2 = fmaxf(M, m2);
        S = S * __expf(M - M2) + s2 * __expf(m2 - M2);
        M = M2;
    }
    if (lane == 0) { sm_m[w] = M; sm_s[w] = S; }
    __syncthreads();
    if (t == 0) {
        M = sm_m[0]; S = sm_s[0];
#pragma unroll
        for (int k = 1; k < 32; k++) {
            float m2 = sm_m[k], s2 = sm_s[k];
            float M2 = fmaxf(M, m2);
            S = S * __expf(M - M2) + s2 * __expf(m2 - M2);
            M = M2;
        }
        g_m = M;
        g_inv = 1.0f / S;
    }
}

// ---------------------------------------------------------------------------
// K7: CSR aggregation. Warp per node; sequential pack/dp reads, x[src]
// gather, fused ReLU, single store. No atomics.
// ---------------------------------------------------------------------------
__global__ void k_agg(const float* __restrict__ x, float* __restrict__ out) {
    int n = (int)(((long long)blockIdx.x * blockDim.x + threadIdx.x) >> 5);
    int lane = threadIdx.x & 31;
    if (n >= N_NODES) return;
    float m = g_m;
    float inv = g_inv;
    int beg = g_row[n], end = g_row[n + 1];
    float ax = 0.f, ay = 0.f, az = 0.f, aw = 0.f;
    for (int i = beg; i < end; i++) {
        int pk = g_pack[i];
        int src = pk & 0x1FFFF;
        int r = pk >> 17;
        float coef = __expf(g_dp[i] - m) * inv;
        const float4 xs = *(const float4*)(x + (long long)src * E_HID + lane * 4);
        const float4 rr = *(const float4*)(g_remb + (long long)r * E_HID + lane * 4);
        ax = fmaf(coef, xs.x + rr.x, ax);
        ay = fmaf(coef, xs.y + rr.y, ay);
        az = fmaf(coef, xs.z + rr.z, az);
        aw = fmaf(coef, xs.w + rr.w, aw);
    }
    float4* o = (float4*)(out + (long long)n * E_HID) + lane;
    *o = make_float4(fmaxf(ax, 0.f), fmaxf(ay, 0.f), fmaxf(az, 0.f), fmaxf(aw, 0.f));
}

extern "C" void kernel_launch(void* const* d_in, const int* in_sizes, int n_in,
                              void* d_out, int out_size) {
    const float* x       = (const float*)d_in[0];   // [50000,128] f32
    const int*   ei      = (const int*)d_in[1];     // [2,600000] int32
    const int*   et      = (const int*)d_in[2];     // [600000] int32
    const float* rel_emb = (const float*)d_in[3];   // [500,128]
    const float* res_att = (const float*)d_in[4];   // [600000]
    const float* ww_w    = (const float*)d_in[5];   // [128,128]
    const float* rel_w   = (const float*)d_in[6];   // [128,128]
    float* out = (float*)d_out;

    (void)in_sizes; (void)n_in; (void)out_size;

    k_init<<<2048, 256>>>(out, res_att);
    k_rel<<<REL_NUM, E_HID>>>(rel_emb, ww_w, rel_w, out);

    // CSR-by-dst build with packed (rel,src) payload
    k_hist<<<1024, 256>>>(ei);
    k_scan_a<<<SCAN_NB, SCAN_B>>>();
    k_scan_b<<<1, 64>>>();
    k_scan_c<<<SCAN_NB, SCAN_B>>>();
    k_fill<<<1024, 256>>>(ei, et);

    // dot products + fused online softmax stats, then tiny combine
    k_dp_csr<<<DP_NB, DP_BLK>>>(x);
    k_combine<<<1, 1024>>>();

    // atomic-free aggregation (ReLU fused)
    k_agg<<<DP_NB, DP_BLK>>>(x, out);
}

// round 8
// speedup vs baseline: 1.3473x; 1.0916x over previous
#include <cuda_runtime.h>

#define N_NODES 50000
#define N_EDGES 600000
#define REL_NUM 500
#define E_HID   128

#define SCAN_B   1024
#define SCAN_NB  ((N_NODES + SCAN_B - 1) / SCAN_B)   // 49

#define DP_BLK    256
#define DP_WARPS  (DP_BLK / 32)
#define DP_NB     ((N_NODES + DP_WARPS - 1) / DP_WARPS)  // 6250

// output layout: x_e [50000*128] | rel_out [500*128] | res_att [600000]
#define REL_OFF (N_NODES * E_HID)
#define RES_OFF (REL_OFF + REL_NUM * E_HID)

// scratch (device globals: no allocations allowed)
__device__ float g_remb[REL_NUM * E_HID];  // r_emb = rel_emb @ ww_w.T
__device__ int   g_pack[N_EDGES];          // (rel<<17)|src, CSR order
__device__ int   g_cnt[N_NODES];           // in-degree histogram
__device__ int   g_row[N_NODES + 1];       // CSR row offsets
__device__ int   g_cur[N_NODES];           // fill cursors
__device__ int   g_bsum[SCAN_NB];
__device__ int   g_boff[SCAN_NB];
__device__ float g_nm[N_NODES];            // per-node local max m_n
__device__ float g_pmax[DP_NB];            // per-block softmax partials
__device__ float g_psum[DP_NB];
__device__ float g_m;                      // global max
__device__ float g_inv;                    // 1 / global sum

// ---------------------------------------------------------------------------
// K0: copy res_att, zero histogram
// ---------------------------------------------------------------------------
__global__ void k_init(float* __restrict__ out, const float* __restrict__ res_att) {
    int i = blockIdx.x * blockDim.x + threadIdx.x;
    int stride = gridDim.x * blockDim.x;
    for (int j = i; j < N_EDGES; j += stride) out[RES_OFF + j] = res_att[j];
    for (int j = i; j < N_NODES; j += stride) g_cnt[j] = 0;
}

// ---------------------------------------------------------------------------
// K1: r_emb = rel_emb @ ww_w.T (scratch);  rel_out = rel_emb @ rel_w.T (out)
// ---------------------------------------------------------------------------
__global__ void k_rel(const float* __restrict__ rel_emb,
                      const float* __restrict__ ww_w,
                      const float* __restrict__ rel_w,
                      float* __restrict__ out) {
    __shared__ float row[E_HID];
    int r = blockIdx.x, t = threadIdx.x;
    row[t] = rel_emb[r * E_HID + t];
    __syncthreads();
    float a = 0.f, b = 0.f;
#pragma unroll 8
    for (int k = 0; k < E_HID; k++) {
        float v = row[k];
        a = fmaf(v, ww_w[t * E_HID + k], a);
        b = fmaf(v, rel_w[t * E_HID + k], b);
    }
    g_remb[r * E_HID + t] = a;
    out[REL_OFF + r * E_HID + t] = b;
}

// ---------------------------------------------------------------------------
// K2: in-degree histogram over dst
// ---------------------------------------------------------------------------
__global__ void k_hist(const int* __restrict__ ei) {
    int i = blockIdx.x * blockDim.x + threadIdx.x;
    int stride = gridDim.x * blockDim.x;
    for (int e = i; e < N_EDGES; e += stride)
        atomicAdd(&g_cnt[ei[N_EDGES + e]], 1);
}

// ---------------------------------------------------------------------------
// K3a/b/c: 3-phase exclusive scan of g_cnt -> g_row, g_cur
// ---------------------------------------------------------------------------
__global__ void k_scan_a() {
    __shared__ int warp_sums[32];
    int t = threadIdx.x;
    int lane = t & 31, w = t >> 5;
    int idx = blockIdx.x * SCAN_B + t;
    int v = (idx < N_NODES) ? g_cnt[idx] : 0;
    int xv = v;
#pragma unroll
    for (int o = 1; o < 32; o <<= 1) {
        int y = __shfl_up_sync(0xffffffffu, xv, o);
        if (lane >= o) xv += y;
    }
    if (lane == 31) warp_sums[w] = xv;
    __syncthreads();
    if (w == 0) {
        int ws = warp_sums[lane];
#pragma unroll
        for (int o = 1; o < 32; o <<= 1) {
            int y = __shfl_up_sync(0xffffffffu, ws, o);
            if (lane >= o) ws += y;
        }
        warp_sums[lane] = ws;
    }
    __syncthreads();
    int excl = xv - v + (w > 0 ? warp_sums[w - 1] : 0);
    if (idx < N_NODES) g_row[idx] = excl;
    if (t == SCAN_B - 1) g_bsum[blockIdx.x] = excl + v;
}

__global__ void k_scan_b() {
    __shared__ int warp_sums[2];
    int t = threadIdx.x;             // 64 threads
    int lane = t & 31, w = t >> 5;
    int v = (t < SCAN_NB) ? g_bsum[t] : 0;
    int xv = v;
#pragma unroll
    for (int o = 1; o < 32; o <<= 1) {
        int y = __shfl_up_sync(0xffffffffu, xv, o);
        if (lane >= o) xv += y;
    }
    if (lane == 31) warp_sums[w] = xv;
    __syncthreads();
    int excl = xv - v + (w > 0 ? warp_sums[0] : 0);
    if (t < SCAN_NB) g_boff[t] = excl;
}

__global__ void k_scan_c() {
    int idx = blockIdx.x * SCAN_B + threadIdx.x;
    if (idx < N_NODES) {
        int v = g_row[idx] + g_boff[blockIdx.x];
        g_row[idx] = v;
        g_cur[idx] = v;
    }
    if (idx == 0) g_row[N_NODES] = N_EDGES;
}

// ---------------------------------------------------------------------------
// K4: fill packed CSR payload: (rel<<17)|src per slot, grouped by dst
// ---------------------------------------------------------------------------
__global__ void k_fill(const int* __restrict__ ei, const int* __restrict__ et) {
    int i = blockIdx.x * blockDim.x + threadIdx.x;
    int stride = gridDim.x * blockDim.x;
    for (int e = i; e < N_EDGES; e += stride) {
        int dst = ei[N_EDGES + e];
        int pos = atomicAdd(&g_cur[dst], 1);
        g_pack[pos] = ei[e] | (et[e] << 17);
    }
}

// ---------------------------------------------------------------------------
// K5: FUSED pass (flash-attention style). Warp per node:
//   - x[dst] loaded once into registers
//   - per in-edge: h = x[src]+r_emb, dot with x[dst], online-rescaled
//     accumulator acc += exp(p - m_n) * h   (rescale acc on new max)
//   - write unnormalized acc into out, m_n per node, block (m,s) partials.
// One gather pass total — no g_dp, no second gather.
// ---------------------------------------------------------------------------
__global__ void k_fused(const float* __restrict__ x, float* __restrict__ out) {
    __shared__ float sm_m[DP_WARPS], sm_s[DP_WARPS];
    int n = (int)(((long long)blockIdx.x * blockDim.x + threadIdx.x) >> 5);
    int lane = threadIdx.x & 31;
    int w = threadIdx.x >> 5;

    float m_w = -3.4e38f, s_w = 0.f;   // per-node (m, s); one node per warp
    if (n < N_NODES) {
        int beg = g_row[n], end = g_row[n + 1];
        const float4 xd = *(const float4*)(x + (long long)n * E_HID + lane * 4);
        float ax = 0.f, ay = 0.f, az = 0.f, aw = 0.f;
        for (int i = beg; i < end; i++) {
            int pk = g_pack[i];
            int src = pk & 0x1FFFF;
            int r = pk >> 17;
            const float4 xs = *(const float4*)(x + (long long)src * E_HID + lane * 4);
            const float4 rr = *(const float4*)(g_remb + (long long)r * E_HID + lane * 4);
            float hx = xs.x + rr.x, hy = xs.y + rr.y;
            float hz = xs.z + rr.z, hw = xs.w + rr.w;
            float p = hx * xd.x + hy * xd.y + hz * xd.z + hw * xd.w;
#pragma unroll
            for (int o = 16; o; o >>= 1) p += __shfl_xor_sync(0xffffffffu, p, o);
            // online rescale (p identical across lanes)
            if (p > m_w) {
                float sc = __expf(m_w - p);
                ax *= sc; ay *= sc; az *= sc; aw *= sc;
                s_w *= sc;
                m_w = p;
            }
            float c = __expf(p - m_w);
            s_w += c;
            ax = fmaf(c, hx, ax);
            ay = fmaf(c, hy, ay);
            az = fmaf(c, hz, az);
            aw = fmaf(c, hw, aw);
        }
        float4* o = (float4*)(out + (long long)n * E_HID) + lane;
        *o = make_float4(ax, ay, az, aw);     // unnormalized
        if (lane == 0) g_nm[n] = m_w;
    }
    if (lane == 0) { sm_m[w] = m_w; sm_s[w] = s_w; }
    __syncthreads();
    if (threadIdx.x == 0) {
        float M = sm_m[0], S = sm_s[0];
#pragma unroll
        for (int k = 1; k < DP_WARPS; k++) {
            float m2 = sm_m[k], s2 = sm_s[k];
            float M2 = fmaxf(M, m2);
            S = S * __expf(M - M2) + s2 * __expf(m2 - M2);
            M = M2;
        }
        g_pmax[blockIdx.x] = M;
        g_psum[blockIdx.x] = S;
    }
}

// ---------------------------------------------------------------------------
// K6: combine per-block (m, s) partials -> g_m, g_inv. Single block.
// ---------------------------------------------------------------------------
__global__ void k_combine() {
    __shared__ float sm_m[32], sm_s[32];
    int t = threadIdx.x;             // 1024
    int lane = t & 31, w = t >> 5;
    float M = -3.4e38f, S = 0.f;
    for (int i = t; i < DP_NB; i += 1024) {
        float m2 = g_pmax[i], s2 = g_psum[i];
        float M2 = fmaxf(M, m2);
        S = S * __expf(M - M2) + s2 * __expf(m2 - M2);
        M = M2;
    }
#pragma unroll
    for (int o = 16; o; o >>= 1) {
        float m2 = __shfl_xor_sync(0xffffffffu, M, o);
        float s2 = __shfl_xor_sync(0xffffffffu, S, o);
        float M2 = fmaxf(M, m2);
        S = S * __expf(M - M2) + s2 * __expf(m2 - M2);
        M = M2;
    }
    if (lane == 0) { sm_m[w] = M; sm_s[w] = S; }
    __syncthreads();
    if (t == 0) {
        M = sm_m[0]; S = sm_s[0];
#pragma unroll
        for (int k = 1; k < 32; k++) {
            float m2 = sm_m[k], s2 = sm_s[k];
            float M2 = fmaxf(M, m2);
            S = S * __expf(M - M2) + s2 * __expf(m2 - M2);
            M = M2;
        }
        g_m = M;
        g_inv = 1.0f / S;
    }
}

// ---------------------------------------------------------------------------
// K7: final scale: out[n,:] *= exp(m_n - M) / S, then ReLU. Streaming 51MB.
// Warp per node (float4 per lane) so the per-node scale is computed once.
// ---------------------------------------------------------------------------
__global__ void k_scale(float* __restrict__ out) {
    int n = (int)(((long long)blockIdx.x * blockDim.x + threadIdx.x) >> 5);
    int lane = threadIdx.x & 31;
    if (n >= N_NODES) return;
    float sc = __expf(g_nm[n] - g_m) * g_inv;
    float4* o = (float4*)(out + (long long)n * E_HID) + lane;
    float4 v = *o;
    *o = make_float4(fmaxf(v.x * sc, 0.f), fmaxf(v.y * sc, 0.f),
                     fmaxf(v.z * sc, 0.f), fmaxf(v.w * sc, 0.f));
}

extern "C" void kernel_launch(void* const* d_in, const int* in_sizes, int n_in,
                              void* d_out, int out_size) {
    const float* x       = (const float*)d_in[0];   // [50000,128] f32
    const int*   ei      = (const int*)d_in[1];     // [2,600000] int32
    const int*   et      = (const int*)d_in[2];     // [600000] int32
    const float* rel_emb = (const float*)d_in[3];   // [500,128]
    const float* res_att = (const float*)d_in[4];   // [600000]
    const float* ww_w    = (const float*)d_in[5];   // [128,128]
    const float* rel_w   = (const float*)d_in[6];   // [128,128]
    float* out = (float*)d_out;

    (void)in_sizes; (void)n_in; (void)out_size;

    k_init<<<2048, 256>>>(out, res_att);
    k_rel<<<REL_NUM, E_HID>>>(rel_emb, ww_w, rel_w, out);

    // CSR-by-dst build with packed (rel,src) payload
    k_hist<<<1024, 256>>>(ei);
    k_scan_a<<<SCAN_NB, SCAN_B>>>();
    k_scan_b<<<1, 64>>>();
    k_scan_c<<<SCAN_NB, SCAN_B>>>();
    k_fill<<<1024, 256>>>(ei, et);

    // single fused gather pass (dot + online softmax + aggregation)
    k_fused<<<DP_NB, DP_BLK>>>(x, out);
    k_combine<<<1, 1024>>>();
    k_scale<<<DP_NB, DP_BLK>>>(out);
}

// round 11
// speedup vs baseline: 1.3662x; 1.0141x over previous
#include <cuda_runtime.h>

#define N_NODES 50000
#define N_EDGES 600000
#define REL_NUM 500
#define E_HID   128

#define SCAN_B   1024
#define SCAN_NB  ((N_NODES + SCAN_B - 1) / SCAN_B)   // 49

#define DP_BLK    256
#define DP_WARPS  (DP_BLK / 32)
#define DP_NB     ((N_NODES + DP_WARPS - 1) / DP_WARPS)  // 6250

// output layout: x_e [50000*128] | rel_out [500*128] | res_att [600000]
#define REL_OFF (N_NODES * E_HID)
#define RES_OFF (REL_OFF + REL_NUM * E_HID)

// scratch (device globals: no allocations allowed)
__device__ float g_remb[REL_NUM * E_HID];  // r_emb = rel_emb @ ww_w.T
__device__ int   g_pack[N_EDGES];          // (rel<<17)|src, CSR order
__device__ int   g_cnt[N_NODES];           // in-degree histogram
__device__ int   g_row[N_NODES + 1];       // CSR row offsets
__device__ int   g_cur[N_NODES];           // fill cursors
__device__ int   g_bsum[SCAN_NB];
__device__ int   g_boff[SCAN_NB];
__device__ float g_nm[N_NODES];            // per-node running max m_n
__device__ float g_pmax[DP_NB];            // per-block softmax partials
__device__ float g_psum[DP_NB];
__device__ float g_m;                      // global max
__device__ float g_inv;                    // 1 / global sum

// warp-wide float add reduction (shfl butterfly; redux.f32 not on sm_103)
__device__ __forceinline__ float warp_sum(float v) {
#pragma unroll
    for (int o = 16; o; o >>= 1) v += __shfl_xor_sync(0xffffffffu, v, o);
    return v;
}

// ---------------------------------------------------------------------------
// K0: copy res_att, zero histogram
// ---------------------------------------------------------------------------
__global__ void k_init(float* __restrict__ out, const float* __restrict__ res_att) {
    int i = blockIdx.x * blockDim.x + threadIdx.x;
    int stride = gridDim.x * blockDim.x;
    for (int j = i; j < N_EDGES; j += stride) out[RES_OFF + j] = res_att[j];
    for (int j = i; j < N_NODES; j += stride) g_cnt[j] = 0;
}

// ---------------------------------------------------------------------------
// K1: r_emb = rel_emb @ ww_w.T (scratch);  rel_out = rel_emb @ rel_w.T (out)
// ---------------------------------------------------------------------------
__global__ void k_rel(const float* __restrict__ rel_emb,
                      const float* __restrict__ ww_w,
                      const float* __restrict__ rel_w,
                      float* __restrict__ out) {
    __shared__ float row[E_HID];
    int r = blockIdx.x, t = threadIdx.x;
    row[t] = rel_emb[r * E_HID + t];
    __syncthreads();
    float a = 0.f, b = 0.f;
#pragma unroll 8
    for (int k = 0; k < E_HID; k++) {
        float v = row[k];
        a = fmaf(v, ww_w[t * E_HID + k], a);
        b = fmaf(v, rel_w[t * E_HID + k], b);
    }
    g_remb[r * E_HID + t] = a;
    out[REL_OFF + r * E_HID + t] = b;
}

// ---------------------------------------------------------------------------
// K2: in-degree histogram over dst
// ---------------------------------------------------------------------------
__global__ void k_hist(const int* __restrict__ ei) {
    int i = blockIdx.x * blockDim.x + threadIdx.x;
    int stride = gridDim.x * blockDim.x;
    for (int e = i; e < N_EDGES; e += stride)
        atomicAdd(&g_cnt[ei[N_EDGES + e]], 1);
}

// ---------------------------------------------------------------------------
// K3a/b/c: 3-phase exclusive scan of g_cnt -> g_row, g_cur
// ---------------------------------------------------------------------------
__global__ void k_scan_a() {
    __shared__ int warp_sums[32];
    int t = threadIdx.x;
    int lane = t & 31, w = t >> 5;
    int idx = blockIdx.x * SCAN_B + t;
    int v = (idx < N_NODES) ? g_cnt[idx] : 0;
    int xv = v;
#pragma unroll
    for (int o = 1; o < 32; o <<= 1) {
        int y = __shfl_up_sync(0xffffffffu, xv, o);
        if (lane >= o) xv += y;
    }
    if (lane == 31) warp_sums[w] = xv;
    __syncthreads();
    if (w == 0) {
        int ws = warp_sums[lane];
#pragma unroll
        for (int o = 1; o < 32; o <<= 1) {
            int y = __shfl_up_sync(0xffffffffu, ws, o);
            if (lane >= o) ws += y;
        }
        warp_sums[lane] = ws;
    }
    __syncthreads();
    int excl = xv - v + (w > 0 ? warp_sums[w - 1] : 0);
    if (idx < N_NODES) g_row[idx] = excl;
    if (t == SCAN_B - 1) g_bsum[blockIdx.x] = excl + v;
}

__global__ void k_scan_b() {
    __shared__ int warp_sums[2];
    int t = threadIdx.x;             // 64 threads
    int lane = t & 31, w = t >> 5;
    int v = (t < SCAN_NB) ? g_bsum[t] : 0;
    int xv = v;
#pragma unroll
    for (int o = 1; o < 32; o <<= 1) {
        int y = __shfl_up_sync(0xffffffffu, xv, o);
        if (lane >= o) xv += y;
    }
    if (lane == 31) warp_sums[w] = xv;
    __syncthreads();
    int excl = xv - v + (w > 0 ? warp_sums[0] : 0);
    if (t < SCAN_NB) g_boff[t] = excl;
}

__global__ void k_scan_c() {
    int idx = blockIdx.x * SCAN_B + threadIdx.x;
    if (idx < N_NODES) {
        int v = g_row[idx] + g_boff[blockIdx.x];
        g_row[idx] = v;
        g_cur[idx] = v;
    }
    if (idx == 0) g_row[N_NODES] = N_EDGES;
}

// ---------------------------------------------------------------------------
// K4: fill packed CSR payload: (rel<<17)|src per slot, grouped by dst
// ---------------------------------------------------------------------------
__global__ void k_fill(const int* __restrict__ ei, const int* __restrict__ et) {
    int i = blockIdx.x * blockDim.x + threadIdx.x;
    int stride = gridDim.x * blockDim.x;
    for (int e = i; e < N_EDGES; e += stride) {
        int dst = ei[N_EDGES + e];
        int pos = atomicAdd(&g_cur[dst], 1);
        g_pack[pos] = ei[e] | (et[e] << 17);
    }
}

// ---------------------------------------------------------------------------
// K5: FUSED pass, BRANCHLESS online softmax. Warp per node:
//   - x[dst] loaded once into registers
//   - per edge: p = dot (butterfly, independent of acc chain);
//     m2 = max(m, p); sc = exp(m-m2) (==1 when max unchanged);
//     c = exp(p-m2); s = s*sc + c; acc = acc*sc + c*h; m = m2.
//   Overflow-safe (args to exp always <= 0), no data-dependent branch,
//   acc carried chain is just FMUL+FFMA.
// ---------------------------------------------------------------------------
__global__ void k_fused(const float* __restrict__ x, float* __restrict__ out) {
    __shared__ float sm_m[DP_WARPS], sm_s[DP_WARPS];
    int n = (int)(((long long)blockIdx.x * blockDim.x + threadIdx.x) >> 5);
    int lane = threadIdx.x & 31;
    int w = threadIdx.x >> 5;

    float m_w = -3.4e38f, s_w = 0.f;
    if (n < N_NODES) {
        int beg = g_row[n], end = g_row[n + 1];
        const float4 xd = *(const float4*)(x + (long long)n * E_HID + lane * 4);
        float ax = 0.f, ay = 0.f, az = 0.f, aw = 0.f;
#pragma unroll 2
        for (int i = beg; i < end; i++) {
            int pk = g_pack[i];
            int src = pk & 0x1FFFF;
            int r = pk >> 17;
            const float4 xs = *(const float4*)(x + (long long)src * E_HID + lane * 4);
            const float4 rr = *(const float4*)(g_remb + (long long)r * E_HID + lane * 4);
            float hx = xs.x + rr.x, hy = xs.y + rr.y;
            float hz = xs.z + rr.z, hw = xs.w + rr.w;
            float p = warp_sum(hx * xd.x + hy * xd.y + hz * xd.z + hw * xd.w);
            float m2 = fmaxf(m_w, p);
            float sc = __expf(m_w - m2);   // 1.0 when max unchanged
            float c = __expf(p - m2);
            s_w = s_w * sc + c;
            ax = fmaf(c, hx, ax * sc);
            ay = fmaf(c, hy, ay * sc);
            az = fmaf(c, hz, az * sc);
            aw = fmaf(c, hw, aw * sc);
            m_w = m2;
        }
        float4* o = (float4*)(out + (long long)n * E_HID) + lane;
        *o = make_float4(ax, ay, az, aw);     // unnormalized
        if (lane == 0) g_nm[n] = m_w;
    }
    if (lane == 0) { sm_m[w] = m_w; sm_s[w] = s_w; }
    __syncthreads();
    if (threadIdx.x == 0) {
        float M = sm_m[0], S = sm_s[0];
#pragma unroll
        for (int k = 1; k < DP_WARPS; k++) {
            float m2 = sm_m[k], s2 = sm_s[k];
            float M2 = fmaxf(M, m2);
            S = S * __expf(M - M2) + s2 * __expf(m2 - M2);
            M = M2;
        }
        g_pmax[blockIdx.x] = M;
        g_psum[blockIdx.x] = S;
    }
}

// ---------------------------------------------------------------------------
// K6: combine per-block (m, s) partials -> g_m, g_inv. Single block.
// ---------------------------------------------------------------------------
__global__ void k_combine() {
    __shared__ float sm_m[32], sm_s[32];
    int t = threadIdx.x;             // 1024
    int lane = t & 31, w = t >> 5;
    float M = -3.4e38f, S = 0.f;
    for (int i = t; i < DP_NB; i += 1024) {
        float m2 = g_pmax[i], s2 = g_psum[i];
        float M2 = fmaxf(M, m2);
        S = S * __expf(M - M2) + s2 * __expf(m2 - M2);
        M = M2;
    }
#pragma unroll
    for (int o = 16; o; o >>= 1) {
        float m2 = __shfl_xor_sync(0xffffffffu, M, o);
        float s2 = __shfl_xor_sync(0xffffffffu, S, o);
        float M2 = fmaxf(M, m2);
        S = S * __expf(M - M2) + s2 * __expf(m2 - M2);
        M = M2;
    }
    if (lane == 0) { sm_m[w] = M; sm_s[w] = S; }
    __syncthreads();
    if (t == 0) {
        M = sm_m[0]; S = sm_s[0];
#pragma unroll
        for (int k = 1; k < 32; k++) {
            float m2 = sm_m[k], s2 = sm_s[k];
            float M2 = fmaxf(M, m2);
            S = S * __expf(M - M2) + s2 * __expf(m2 - M2);
            M = M2;
        }
        g_m = M;
        g_inv = 1.0f / S;
    }
}

// ---------------------------------------------------------------------------
// K7: final scale: out[n,:] *= exp(m_n - M) / S, then ReLU. Streaming 51MB.
// ---------------------------------------------------------------------------
__global__ void k_scale(float* __restrict__ out) {
    int n = (int)(((long long)blockIdx.x * blockDim.x + threadIdx.x) >> 5);
    int lane = threadIdx.x & 31;
    if (n >= N_NODES) return;
    float sc = __expf(g_nm[n] - g_m) * g_inv;
    float4* o = (float4*)(out + (long long)n * E_HID) + lane;
    float4 v = *o;
    *o = make_float4(fmaxf(v.x * sc, 0.f), fmaxf(v.y * sc, 0.f),
                     fmaxf(v.z * sc, 0.f), fmaxf(v.w * sc, 0.f));
}

extern "C" void kernel_launch(void* const* d_in, const int* in_sizes, int n_in,
                              void* d_out, int out_size) {
    const float* x       = (const float*)d_in[0];   // [50000,128] f32
    const int*   ei      = (const int*)d_in[1];     // [2,600000] int32
    const int*   et      = (const int*)d_in[2];     // [600000] int32
    const float* rel_emb = (const float*)d_in[3];   // [500,128]
    const float* res_att = (const float*)d_in[4];   // [600000]
    const float* ww_w    = (const float*)d_in[5];   // [128,128]
    const float* rel_w   = (const float*)d_in[6];   // [128,128]
    float* out = (float*)d_out;

    (void)in_sizes; (void)n_in; (void)out_size;

    k_init<<<2048, 256>>>(out, res_att);
    k_rel<<<REL_NUM, E_HID>>>(rel_emb, ww_w, rel_w, out);

    // CSR-by-dst build with packed (rel,src) payload
    k_hist<<<1024, 256>>>(ei);
    k_scan_a<<<SCAN_NB, SCAN_B>>>();
    k_scan_b<<<1, 64>>>();
    k_scan_c<<<SCAN_NB, SCAN_B>>>();
    k_fill<<<1024, 256>>>(ei, et);

    // single fused gather pass (dot + branchless online softmax + aggregation)
    k_fused<<<DP_NB, DP_BLK>>>(x, out);
    k_combine<<<1, 1024>>>();
    k_scale<<<DP_NB, DP_BLK>>>(out);
}

// round 13
// speedup vs baseline: 1.4738x; 1.0787x over previous
#include <cuda_runtime.h>

#define N_NODES 50000
#define N_EDGES 600000
#define REL_NUM 500
#define E_HID   128

#define SCAN_B   1024
#define SCAN_NB  ((N_NODES + SCAN_B - 1) / SCAN_B)   // 49

#define DP_BLK    256
#define DP_WARPS  (DP_BLK / 32)
#define DP_NB     ((N_NODES + DP_WARPS - 1) / DP_WARPS)  // 6250

// output layout: x_e [50000*128] | rel_out [500*128] | res_att [600000]
#define REL_OFF (N_NODES * E_HID)
#define RES_OFF (REL_OFF + REL_NUM * E_HID)

// scratch (device globals: no allocations allowed)
__device__ float g_remb[REL_NUM * E_HID];  // r_emb = rel_emb @ ww_w.T
__device__ int   g_pack[N_EDGES];          // (rel<<17)|src, CSR order
__device__ int   g_cnt[N_NODES];           // in-degree histogram
__device__ int   g_row[N_NODES + 1];       // CSR row offsets
__device__ int   g_cur[N_NODES];           // fill cursors
__device__ int   g_bsum[SCAN_NB];
__device__ int   g_boff[SCAN_NB];
__device__ float g_nm[N_NODES];            // per-node running max m_n
__device__ float g_pmax[DP_NB];            // per-block softmax partials
__device__ float g_psum[DP_NB];
__device__ float g_m;                      // global max
__device__ float g_inv;                    // 1 / global sum

// warp-wide float add reduction (shfl butterfly; redux.f32 not on sm_103)
__device__ __forceinline__ float warp_sum(float v) {
#pragma unroll
    for (int o = 16; o; o >>= 1) v += __shfl_xor_sync(0xffffffffu, v, o);
    return v;
}

// ---------------------------------------------------------------------------
// K0: copy res_att, zero histogram
// ---------------------------------------------------------------------------
__global__ void k_init(float* __restrict__ out, const float* __restrict__ res_att) {
    int i = blockIdx.x * blockDim.x + threadIdx.x;
    int stride = gridDim.x * blockDim.x;
    for (int j = i; j < N_EDGES; j += stride) out[RES_OFF + j] = res_att[j];
    for (int j = i; j < N_NODES; j += stride) g_cnt[j] = 0;
}

// ---------------------------------------------------------------------------
// K1: r_emb = rel_emb @ ww_w.T (scratch);  rel_out = rel_emb @ rel_w.T (out)
// ---------------------------------------------------------------------------
__global__ void k_rel(const float* __restrict__ rel_emb,
                      const float* __restrict__ ww_w,
                      const float* __restrict__ rel_w,
                      float* __restrict__ out) {
    __shared__ float row[E_HID];
    int r = blockIdx.x, t = threadIdx.x;
    row[t] = rel_emb[r * E_HID + t];
    __syncthreads();
    float a = 0.f, b = 0.f;
#pragma unroll 8
    for (int k = 0; k < E_HID; k++) {
        float v = row[k];
        a = fmaf(v, ww_w[t * E_HID + k], a);
        b = fmaf(v, rel_w[t * E_HID + k], b);
    }
    g_remb[r * E_HID + t] = a;
    out[REL_OFF + r * E_HID + t] = b;
}

// ---------------------------------------------------------------------------
// K2: in-degree histogram over dst
// ---------------------------------------------------------------------------
__global__ void k_hist(const int* __restrict__ ei) {
    int i = blockIdx.x * blockDim.x + threadIdx.x;
    int stride = gridDim.x * blockDim.x;
    for (int e = i; e < N_EDGES; e += stride)
        atomicAdd(&g_cnt[ei[N_EDGES + e]], 1);
}

// ---------------------------------------------------------------------------
// K3a/b/c: 3-phase exclusive scan of g_cnt -> g_row, g_cur
// ---------------------------------------------------------------------------
__global__ void k_scan_a() {
    __shared__ int warp_sums[32];
    int t = threadIdx.x;
    int lane = t & 31, w = t >> 5;
    int idx = blockIdx.x * SCAN_B + t;
    int v = (idx < N_NODES) ? g_cnt[idx] : 0;
    int xv = v;
#pragma unroll
    for (int o = 1; o < 32; o <<= 1) {
        int y = __shfl_up_sync(0xffffffffu, xv, o);
        if (lane >= o) xv += y;
    }
    if (lane == 31) warp_sums[w] = xv;
    __syncthreads();
    if (w == 0) {
        int ws = warp_sums[lane];
#pragma unroll
        for (int o = 1; o < 32; o <<= 1) {
            int y = __shfl_up_sync(0xffffffffu, ws, o);
            if (lane >= o) ws += y;
        }
        warp_sums[lane] = ws;
    }
    __syncthreads();
    int excl = xv - v + (w > 0 ? warp_sums[w - 1] : 0);
    if (idx < N_NODES) g_row[idx] = excl;
    if (t == SCAN_B - 1) g_bsum[blockIdx.x] = excl + v;
}

__global__ void k_scan_b() {
    __shared__ int warp_sums[2];
    int t = threadIdx.x;             // 64 threads
    int lane = t & 31, w = t >> 5;
    int v = (t < SCAN_NB) ? g_bsum[t] : 0;
    int xv = v;
#pragma unroll
    for (int o = 1; o < 32; o <<= 1) {
        int y = __shfl_up_sync(0xffffffffu, xv, o);
        if (lane >= o) xv += y;
    }
    if (lane == 31) warp_sums[w] = xv;
    __syncthreads();
    int excl = xv - v + (w > 0 ? warp_sums[0] : 0);
    if (t < SCAN_NB) g_boff[t] = excl;
}

__global__ void k_scan_c() {
    int idx = blockIdx.x * SCAN_B + threadIdx.x;
    if (idx < N_NODES) {
        int v = g_row[idx] + g_boff[blockIdx.x];
        g_row[idx] = v;
        g_cur[idx] = v;
    }
    if (idx == 0) g_row[N_NODES] = N_EDGES;
}

// ---------------------------------------------------------------------------
// K4: fill packed CSR payload: (rel<<17)|src per slot, grouped by dst
// ---------------------------------------------------------------------------
__global__ void k_fill(const int* __restrict__ ei, const int* __restrict__ et) {
    int i = blockIdx.x * blockDim.x + threadIdx.x;
    int stride = gridDim.x * blockDim.x;
    for (int e = i; e < N_EDGES; e += stride) {
        int dst = ei[N_EDGES + e];
        int pos = atomicAdd(&g_cur[dst], 1);
        g_pack[pos] = ei[e] | (et[e] << 17);
    }
}

// ---------------------------------------------------------------------------
// K5: FUSED pass, batch-4 edges per iteration for MLP.
//   - 8 gathered LDG.128 issued before compute (L2 latency overlapped)
//   - 4 independent dot butterflies (pipelined)
//   - ONE online-softmax rescale per batch of 4
// ---------------------------------------------------------------------------
__global__ void k_fused(const float* __restrict__ x, float* __restrict__ out) {
    __shared__ float sm_m[DP_WARPS], sm_s[DP_WARPS];
    int n = (int)(((long long)blockIdx.x * blockDim.x + threadIdx.x) >> 5);
    int lane = threadIdx.x & 31;
    int w = threadIdx.x >> 5;

    float m_w = -3.4e38f, s_w = 0.f;
    if (n < N_NODES) {
        int beg = g_row[n], end = g_row[n + 1];
        const float4 xd = *(const float4*)(x + (long long)n * E_HID + lane * 4);
        float ax = 0.f, ay = 0.f, az = 0.f, aw = 0.f;

        int i = beg;
        for (; i + 4 <= end; i += 4) {
            int pk0 = g_pack[i + 0], pk1 = g_pack[i + 1];
            int pk2 = g_pack[i + 2], pk3 = g_pack[i + 3];
            const float4 a0 = *(const float4*)(x + (long long)(pk0 & 0x1FFFF) * E_HID + lane * 4);
            const float4 b0 = *(const float4*)(g_remb + (long long)(pk0 >> 17) * E_HID + lane * 4);
            const float4 a1 = *(const float4*)(x + (long long)(pk1 & 0x1FFFF) * E_HID + lane * 4);
            const float4 b1 = *(const float4*)(g_remb + (long long)(pk1 >> 17) * E_HID + lane * 4);
            const float4 a2 = *(const float4*)(x + (long long)(pk2 & 0x1FFFF) * E_HID + lane * 4);
            const float4 b2 = *(const float4*)(g_remb + (long long)(pk2 >> 17) * E_HID + lane * 4);
            const float4 a3 = *(const float4*)(x + (long long)(pk3 & 0x1FFFF) * E_HID + lane * 4);
            const float4 b3 = *(const float4*)(g_remb + (long long)(pk3 >> 17) * E_HID + lane * 4);

            float h0x = a0.x + b0.x, h0y = a0.y + b0.y, h0z = a0.z + b0.z, h0w = a0.w + b0.w;
            float h1x = a1.x + b1.x, h1y = a1.y + b1.y, h1z = a1.z + b1.z, h1w = a1.w + b1.w;
            float h2x = a2.x + b2.x, h2y = a2.y + b2.y, h2z = a2.z + b2.z, h2w = a2.w + b2.w;
            float h3x = a3.x + b3.x, h3y = a3.y + b3.y, h3z = a3.z + b3.z, h3w = a3.w + b3.w;

            float p0 = h0x * xd.x + h0y * xd.y + h0z * xd.z + h0w * xd.w;
            float p1 = h1x * xd.x + h1y * xd.y + h1z * xd.z + h1w * xd.w;
            float p2 = h2x * xd.x + h2y * xd.y + h2z * xd.z + h2w * xd.w;
            float p3 = h3x * xd.x + h3y * xd.y + h3z * xd.z + h3w * xd.w;
            // 4 independent butterflies — pipeline across each other
#pragma unroll
            for (int o = 16; o; o >>= 1) {
                p0 += __shfl_xor_sync(0xffffffffu, p0, o);
                p1 += __shfl_xor_sync(0xffffffffu, p1, o);
                p2 += __shfl_xor_sync(0xffffffffu, p2, o);
                p3 += __shfl_xor_sync(0xffffffffu, p3, o);
            }

            float mb = fmaxf(fmaxf(p0, p1), fmaxf(p2, p3));
            float m2 = fmaxf(m_w, mb);
            float sc = __expf(m_w - m2);        // 1.0 when max unchanged
            float c0 = __expf(p0 - m2), c1 = __expf(p1 - m2);
            float c2 = __expf(p2 - m2), c3 = __expf(p3 - m2);
            s_w = s_w * sc + ((c0 + c1) + (c2 + c3));
            ax = fmaf(c3, h3x, fmaf(c2, h2x, fmaf(c1, h1x, fmaf(c0, h0x, ax * sc))));
            ay = fmaf(c3, h3y, fmaf(c2, h2y, fmaf(c1, h1y, fmaf(c0, h0y, ay * sc))));
            az = fmaf(c3, h3z, fmaf(c2, h2z, fmaf(c1, h1z, fmaf(c0, h0z, az * sc))));
            aw = fmaf(c3, h3w, fmaf(c2, h2w, fmaf(c1, h1w, fmaf(c0, h0w, aw * sc))));
            m_w = m2;
        }
        // remainder (0-3 edges), scalar online softmax
        for (; i < end; i++) {
            int pk = g_pack[i];
            const float4 xs = *(const float4*)(x + (long long)(pk & 0x1FFFF) * E_HID + lane * 4);
            const float4 rr = *(const float4*)(g_remb + (long long)(pk >> 17) * E_HID + lane * 4);
            float hx = xs.x + rr.x, hy = xs.y + rr.y;
            float hz = xs.z + rr.z, hw = xs.w + rr.w;
            float p = warp_sum(hx * xd.x + hy * xd.y + hz * xd.z + hw * xd.w);
            float m2 = fmaxf(m_w, p);
            float sc = __expf(m_w - m2);
            float c = __expf(p - m2);
            s_w = s_w * sc + c;
            ax = fmaf(c, hx, ax * sc);
            ay = fmaf(c, hy, ay * sc);
            az = fmaf(c, hz, az * sc);
            aw = fmaf(c, hw, aw * sc);
            m_w = m2;
        }
        float4* o = (float4*)(out + (long long)n * E_HID) + lane;
        *o = make_float4(ax, ay, az, aw);     // unnormalized
        if (lane == 0) g_nm[n] = m_w;
    }
    if (lane == 0) { sm_m[w] = m_w; sm_s[w] = s_w; }
    __syncthreads();
    if (threadIdx.x == 0) {
        float M = sm_m[0], S = sm_s[0];
#pragma unroll
        for (int k = 1; k < DP_WARPS; k++) {
            float m2 = sm_m[k], s2 = sm_s[k];
            float M2 = fmaxf(M, m2);
            S = S * __expf(M - M2) + s2 * __expf(m2 - M2);
            M = M2;
        }
        g_pmax[blockIdx.x] = M;
        g_psum[blockIdx.x] = S;
    }
}

// ---------------------------------------------------------------------------
// K6: combine per-block (m, s) partials -> g_m, g_inv. Single block.
// ---------------------------------------------------------------------------
__global__ void k_combine() {
    __shared__ float sm_m[32], sm_s[32];
    int t = threadIdx.x;             // 1024
    int lane = t & 31, w = t >> 5;
    float M = -3.4e38f, S = 0.f;
    for (int i = t; i < DP_NB; i += 1024) {
        float m2 = g_pmax[i], s2 = g_psum[i];
        float M2 = fmaxf(M, m2);
        S = S * __expf(M - M2) + s2 * __expf(m2 - M2);
        M = M2;
    }
#pragma unroll
    for (int o = 16; o; o >>= 1) {
        float m2 = __shfl_xor_sync(0xffffffffu, M, o);
        float s2 = __shfl_xor_sync(0xffffffffu, S, o);
        float M2 = fmaxf(M, m2);
        S = S * __expf(M - M2) + s2 * __expf(m2 - M2);
        M = M2;
    }
    if (lane == 0) { sm_m[w] = M; sm_s[w] = S; }
    __syncthreads();
    if (t == 0) {
        M = sm_m[0]; S = sm_s[0];
#pragma unroll
        for (int k = 1; k < 32; k++) {
            float m2 = sm_m[k], s2 = sm_s[k];
            float M2 = fmaxf(M, m2);
            S = S * __expf(M - M2) + s2 * __expf(m2 - M2);
            M = M2;
        }
        g_m = M;
        g_inv = 1.0f / S;
    }
}

// ---------------------------------------------------------------------------
// K7: final scale: out[n,:] *= exp(m_n - M) / S, then ReLU. Streaming 51MB.
// ---------------------------------------------------------------------------
__global__ void k_scale(float* __restrict__ out) {
    int n = (int)(((long long)blockIdx.x * blockDim.x + threadIdx.x) >> 5);
    int lane = threadIdx.x & 31;
    if (n >= N_NODES) return;
    float sc = __expf(g_nm[n] - g_m) * g_inv;
    float4* o = (float4*)(out + (long long)n * E_HID) + lane;
    float4 v = *o;
    *o = make_float4(fmaxf(v.x * sc, 0.f), fmaxf(v.y * sc, 0.f),
                     fmaxf(v.z * sc, 0.f), fmaxf(v.w * sc, 0.f));
}

extern "C" void kernel_launch(void* const* d_in, const int* in_sizes, int n_in,
                              void* d_out, int out_size) {
    const float* x       = (const float*)d_in[0];   // [50000,128] f32
    const int*   ei      = (const int*)d_in[1];     // [2,600000] int32
    const int*   et      = (const int*)d_in[2];     // [600000] int32
    const float* rel_emb = (const float*)d_in[3];   // [500,128]
    const float* res_att = (const float*)d_in[4];   // [600000]
    const float* ww_w    = (const float*)d_in[5];   // [128,128]
    const float* rel_w   = (const float*)d_in[6];   // [128,128]
    float* out = (float*)d_out;

    (void)in_sizes; (void)n_in; (void)out_size;

    k_init<<<2048, 256>>>(out, res_att);
    k_rel<<<REL_NUM, E_HID>>>(rel_emb, ww_w, rel_w, out);

    // CSR-by-dst build with packed (rel,src) payload
    k_hist<<<1024, 256>>>(ei);
    k_scan_a<<<SCAN_NB, SCAN_B>>>();
    k_scan_b<<<1, 64>>>();
    k_scan_c<<<SCAN_NB, SCAN_B>>>();
    k_fill<<<1024, 256>>>(ei, et);

    // single fused gather pass (batch-4 edges, online softmax, aggregation)
    k_fused<<<DP_NB, DP_BLK>>>(x, out);
    k_combine<<<1, 1024>>>();
    k_scale<<<DP_NB, DP_BLK>>>(out);
}